// round 5
// baseline (speedup 1.0000x reference)
#include <cuda_runtime.h>

// Fused conv1 -> conv2 -> SIFT128 -> linear -> softmax, one CTA/image.
// Round 5: warp-specialized conv1 (producer) / conv2 (consumer) with
// double-buffered a1, stride-33 padding (kills 4-way LDS conflicts), FFMA2.

__constant__ float c_b1[32];
__constant__ float c_b2[3];
__constant__ float c_bl[10];

typedef unsigned long long u64;

// packed weights: [0,144) conv1 (w_even,w_odd); [144,576) conv2
__device__ __align__(16) float2 g_wpk[576];

__device__ __forceinline__ void fma2(u64& d, u64 a, u64 b) {
    asm("fma.rn.f32x2 %0, %1, %2, %0;" : "+l"(d) : "l"(a), "l"(b));
}
__device__ __forceinline__ u64 pk2(float lo, float hi) {
    u64 r; asm("mov.b64 %0, {%1, %2};" : "=l"(r) : "f"(lo), "f"(hi)); return r;
}
__device__ __forceinline__ float2 upk(u64 v) {
    float2 f; asm("mov.b64 {%0, %1}, %2;" : "=f"(f.x), "=f"(f.y) : "l"(v)); return f;
}

// shared layout (floats). a1: double buffer, 4 ch-pairs x 26 rows x stride 33 u64.
#define SM_XSPL    0                    // 840 u64 = 1680 f
#define SM_A1P     1680                 // 2 * 3432 u64 = 13728 f
#define SM_A2P     (SM_A1P + 13728)     // 2028
#define SM_CELLS   (SM_A2P + 2028)      // 384
#define SM_NORMS   (SM_CELLS + 384)     // 4
#define SM_LOGITS  (SM_NORMS + 4)       // 12
#define SM_WPK     (SM_LOGITS + 12)     // 17836 (16B aligned), 576 u64 = 1152 f
#define SM_FLOATS  (SM_WPK + 1152)      // 18988 f = 75952 B

#define A1_ROW   33                      // u64 row stride
#define A1_CP    858                     // 26 * 33
#define A1_BUF   3432                    // 4 * 858

__global__ void pack_weights(const float* __restrict__ W1,
                             const float* __restrict__ W2)
{
    int i = threadIdx.x + blockIdx.x * blockDim.x;
    if (i < 144) {
        int p = i / 9, k = i % 9;
        g_wpk[i] = make_float2(W1[(2 * p) * 9 + k], W1[(2 * p + 1) * 9 + k]);
    } else if (i < 576) {
        int j = i - 144;
        int oc = j / 144, r = j % 144;
        int icp = r / 9, tap = r % 9;
        g_wpk[i] = make_float2(W2[oc * 288 + (2 * icp) * 9 + tap],
                               W2[oc * 288 + (2 * icp + 1) * 9 + tap]);
    }
}

// conv1 producer: one thread = 2 ch-pairs x 1 row x 13 cols
__device__ __forceinline__ void conv1_chunk(int chunk, u64* dst,
                                            const u64* xspl, const u64* wpk1, int t)
{
    int cpg  = t / 52;
    int tt   = t % 52;
    int row  = tt >> 1;
    int half = tt & 1;
    int gp0  = chunk * 4 + cpg * 2;
    const u64* ws = wpk1 + gp0 * 9;
    u64 wA[9], wB[9];
#pragma unroll
    for (int k = 0; k < 9; k++) { wA[k] = ws[k]; wB[k] = ws[9 + k]; }
    u64 bpA = pk2(c_b1[2 * gp0],     c_b1[2 * gp0 + 1]);
    u64 bpB = pk2(c_b1[2 * gp0 + 2], c_b1[2 * gp0 + 3]);
    const u64* xr = xspl + row * 30 + half * 13;
    u64 t00 = xr[0],  t01 = xr[1];
    u64 t10 = xr[30], t11 = xr[31];
    u64 t20 = xr[60], t21 = xr[61];
    float2* oA = (float2*)(dst + (cpg * 2) * A1_CP + row * A1_ROW + half * 13);
    float2* oB = oA + A1_CP;
#pragma unroll
    for (int s = 0; s < 13; s++) {
        u64 n0 = xr[s + 2], n1 = xr[s + 32], n2 = xr[s + 62];
        u64 a = bpA, b = bpB;
        fma2(a, t00, wA[0]); fma2(a, t01, wA[1]); fma2(a, n0, wA[2]);
        fma2(a, t10, wA[3]); fma2(a, t11, wA[4]); fma2(a, n1, wA[5]);
        fma2(a, t20, wA[6]); fma2(a, t21, wA[7]); fma2(a, n2, wA[8]);
        fma2(b, t00, wB[0]); fma2(b, t01, wB[1]); fma2(b, n0, wB[2]);
        fma2(b, t10, wB[3]); fma2(b, t11, wB[4]); fma2(b, n1, wB[5]);
        fma2(b, t20, wB[6]); fma2(b, t21, wB[7]); fma2(b, n2, wB[8]);
        float2 fa = upk(a), fb = upk(b);
        oA[s] = make_float2(fmaxf(fa.x, 0.0f), fmaxf(fa.y, 0.0f));
        oB[s] = make_float2(fmaxf(fb.x, 0.0f), fmaxf(fb.y, 0.0f));
        t00 = t01; t01 = n0;
        t10 = t11; t11 = n1;
        t20 = t21; t21 = n2;
    }
}

// conv2 consumer: one thread = 1 out-row x 6-px strip, persistent acc
__device__ __forceinline__ void conv2_chunk(int kc, const u64* src, const u64* wpk2,
                                            int c2row, int c2xb, u64 acc[3][6])
{
#pragma unroll
    for (int icp = 0; icp < 4; icp++) {
        const u64* ap = src + icp * A1_CP + c2row * A1_ROW + c2xb;
        int gicp = kc * 4 + icp;
#pragma unroll
        for (int dy = 0; dy < 3; dy++) {
            u64 v[8];
#pragma unroll
            for (int j = 0; j < 8; j++) v[j] = ap[dy * A1_ROW + j];
#pragma unroll
            for (int oc = 0; oc < 3; oc++) {
                const u64* wo = wpk2 + (oc * 16 + gicp) * 9 + dy * 3;
                u64 wa = wo[0], wb = wo[1], wc = wo[2];
#pragma unroll
                for (int j = 0; j < 6; j++) {
                    fma2(acc[oc][j], v[j],     wa);
                    fma2(acc[oc][j], v[j + 1], wb);
                    fma2(acc[oc][j], v[j + 2], wc);
                }
            }
        }
    }
}

__global__ __launch_bounds__(256, 2)
void fused_sift_net(const float* __restrict__ x,
                    const float* __restrict__ Wl,
                    float* __restrict__ out)
{
    extern __shared__ float sm[];
    const int tid = threadIdx.x;
    const int img = blockIdx.x;

    // ---------------- Phase 0: splat image, stage weights, zero a2 ---------
    {
        const float4* xg = (const float4*)(x + (size_t)img * 784);
        float4* xs = (float4*)&sm[SM_XSPL];
        for (int i4 = tid; i4 < 196; i4 += 256) {
            float4 v = __ldg(&xg[i4]);
            int li = i4 * 4;
            int r = li / 28, c = li % 28;
            int fi = (r * 30 + c) >> 1;
            xs[fi]     = make_float4(v.x, v.x, v.y, v.y);
            xs[fi + 1] = make_float4(v.z, v.z, v.w, v.w);
        }
        const float4* gw = (const float4*)g_wpk;
        float4* swp = (float4*)&sm[SM_WPK];
        for (int i = tid; i < 288; i += 256) swp[i] = __ldg(&gw[i]);
        for (int i = tid; i < 2028; i += 256) sm[SM_A2P + i] = 0.0f;
    }

    const u64* wpk1 = (const u64*)&sm[SM_WPK];
    const u64* wpk2 = wpk1 + 144;
    const u64* xspl = (const u64*)&sm[SM_XSPL];
    u64* a1u = (u64*)&sm[SM_A1P];

    const int c2row = tid >> 2;          // 0..23 (valid tid<96)
    const int c2xb  = (tid & 3) * 6;
    u64 acc[3][6];
    if (tid < 96) {
#pragma unroll
        for (int oc = 0; oc < 3; oc++) {
            u64 bp = pk2(c_b2[oc], 0.0f);
#pragma unroll
            for (int j = 0; j < 6; j++) acc[oc][j] = bp;
        }
    }

    __syncthreads();

    // ---------------- pipelined conv1 (produce) / conv2 (consume) ----------
    if (tid >= 128 && tid < 232)
        conv1_chunk(0, a1u, xspl, wpk1, tid - 128);
    __syncthreads();
#pragma unroll
    for (int k = 1; k < 4; k++) {
        if (tid >= 128 && tid < 232)
            conv1_chunk(k, a1u + (k & 1) * A1_BUF, xspl, wpk1, tid - 128);
        else if (tid < 96)
            conv2_chunk(k - 1, a1u + ((k - 1) & 1) * A1_BUF, wpk2, c2row, c2xb, acc);
        __syncthreads();
    }
    if (tid < 96) {
        conv2_chunk(3, a1u + A1_BUF, wpk2, c2row, c2xb, acc);
        // conv2 outputs -> padded tile (scalar = lo + hi)
#pragma unroll
        for (int oc = 0; oc < 3; oc++) {
            float* dst = &sm[SM_A2P + oc * 676 + (c2row + 1) * 26 + (c2xb + 1)];
#pragma unroll
            for (int j = 0; j < 6; j++) {
                float2 f = upk(acc[oc][j]);
                dst[j] = f.x + f.y;
            }
        }
    }
    __syncthreads();

    // ---------------- Phase 3: SIFT, register histograms --------------------
    if (tid < 192) {
        const float CS[8] = { 0.92387953f,  0.38268343f, -0.38268343f, -0.92387953f,
                             -0.92387953f, -0.38268343f,  0.38268343f,  0.92387953f};
        const float SN[8] = { 0.38268343f,  0.92387953f,  0.92387953f,  0.38268343f,
                             -0.38268343f, -0.92387953f, -0.92387953f, -0.38268343f};
        int p    = tid / 64;
        int rem  = tid % 64;
        int cell = rem >> 2;
        int quad = rem & 3;
        int r0 = (cell >> 2) * 6 + (quad >> 1) * 3;
        int c0 = (cell & 3) * 6 + (quad & 1) * 3;
        const float* ap = &sm[SM_A2P + p * 676 + r0 * 26 + c0];
        float pt[5][5];
#pragma unroll
        for (int i = 0; i < 5; i++)
#pragma unroll
            for (int j = 0; j < 5; j++) pt[i][j] = ap[i * 26 + j];

        float hist[8] = {0,0,0,0,0,0,0,0};
#pragma unroll
        for (int i = 0; i < 3; i++) {
#pragma unroll
            for (int j = 0; j < 3; j++) {
                float Ix = (pt[i][j+2] - pt[i][j])
                         + 2.0f * (pt[i+1][j+2] - pt[i+1][j])
                         + (pt[i+2][j+2] - pt[i+2][j]);
                float Iy = (pt[i+2][j] - pt[i][j])
                         + 2.0f * (pt[i+2][j+1] - pt[i][j+1])
                         + (pt[i+2][j+2] - pt[i][j+2]);
                float mag = sqrtf(Ix * Ix + Iy * Iy + 1e-12f);
                float ck[8];
                float cmax = -1e30f;
#pragma unroll
                for (int k = 0; k < 8; k++) {
                    ck[k] = CS[k] * Ix + SN[k] * Iy;
                    cmax = fmaxf(cmax, ck[k]);
                }
#pragma unroll
                for (int k = 0; k < 8; k++)
                    hist[k] += (ck[k] == cmax) ? mag : 0.0f;
            }
        }
#pragma unroll
        for (int k = 0; k < 8; k++) {
            float v = hist[k];
            v += __shfl_xor_sync(0xffffffffu, v, 1);
            v += __shfl_xor_sync(0xffffffffu, v, 2);
            if (quad == 0)
                sm[SM_CELLS + p * 128 + k * 16 + cell] = v;
        }
    }
    __syncthreads();

    // ---------------- Phase 4: norms + pow 0.9 ------------------------------
    if (tid < 96) {
        int w = tid >> 5, lane = tid & 31;
        const float* cp = &sm[SM_CELLS + w * 128];
        float s = 0.0f;
#pragma unroll
        for (int j = 0; j < 4; j++) {
            float v = cp[lane + 32 * j];
            s = fmaf(v, v, s);
        }
#pragma unroll
        for (int d = 16; d; d >>= 1)
            s += __shfl_xor_sync(0xffffffffu, s, d);
        if (lane == 0) sm[SM_NORMS + w] = sqrtf(s);
    }
    __syncthreads();
    {
        int i = tid;
        if (i < 384) {
            float v = sm[SM_CELLS + i];
            float f = v / (sm[SM_NORMS + (i >> 7)] + 1e-8f);
            sm[SM_CELLS + i] = powf(f + 1e-8f, 0.9f);
        }
        i = tid + 256;
        if (i < 384) {
            float v = sm[SM_CELLS + i];
            float f = v / (sm[SM_NORMS + (i >> 7)] + 1e-8f);
            sm[SM_CELLS + i] = powf(f + 1e-8f, 0.9f);
        }
    }
    __syncthreads();

    // ---------------- Phase 5: 384x10 linear --------------------------------
    {
        int w = tid >> 5, lane = tid & 31;
#pragma unroll
        for (int rep = 0; rep < 2; rep++) {
            int o = w + rep * 8;
            if (o < 10) {
                float s = 0.0f;
                const float* wrow = Wl + o * 384;
                for (int i = lane; i < 384; i += 32)
                    s = fmaf(sm[SM_CELLS + i], __ldg(&wrow[i]), s);
#pragma unroll
                for (int d = 16; d; d >>= 1)
                    s += __shfl_xor_sync(0xffffffffu, s, d);
                if (lane == 0) sm[SM_LOGITS + o] = s + c_bl[o];
            }
        }
    }
    __syncthreads();

    // ---------------- Phase 6: relu + softmax -------------------------------
    if (tid < 32) {
        float v = (tid < 10) ? fmaxf(sm[SM_LOGITS + tid], 0.0f) : -1e30f;
        float m = v;
#pragma unroll
        for (int d = 16; d; d >>= 1)
            m = fmaxf(m, __shfl_xor_sync(0xffffffffu, m, d));
        float e = (tid < 10) ? expf(v - m) : 0.0f;
        float ssum = e;
#pragma unroll
        for (int d = 16; d; d >>= 1)
            ssum += __shfl_xor_sync(0xffffffffu, ssum, d);
        if (tid < 10) out[(size_t)img * 10 + tid] = e / ssum;
    }
}

extern "C" void kernel_launch(void* const* d_in, const int* in_sizes, int n_in,
                              void* d_out, int out_size)
{
    const float* x  = (const float*)d_in[0];
    const float* W1 = (const float*)d_in[1];
    const float* b1 = (const float*)d_in[2];
    const float* W2 = (const float*)d_in[3];
    const float* b2 = (const float*)d_in[4];
    const float* Wl = (const float*)d_in[5];
    const float* bl = (const float*)d_in[6];

    int nimg = in_sizes[0] / 784;

    cudaMemcpyToSymbolAsync(c_b1, b1, 32 * sizeof(float), 0, cudaMemcpyDeviceToDevice, 0);
    cudaMemcpyToSymbolAsync(c_b2, b2,  3 * sizeof(float), 0, cudaMemcpyDeviceToDevice, 0);
    cudaMemcpyToSymbolAsync(c_bl, bl, 10 * sizeof(float), 0, cudaMemcpyDeviceToDevice, 0);

    pack_weights<<<3, 256>>>(W1, W2);

    size_t smem = SM_FLOATS * sizeof(float);
    cudaFuncSetAttribute(fused_sift_net,
                         cudaFuncAttributeMaxDynamicSharedMemorySize, (int)smem);

    fused_sift_net<<<nimg, 256, smem>>>(x, Wl, (float*)d_out);
}

// round 6
// speedup vs baseline: 1.0629x; 1.0629x over previous
#include <cuda_runtime.h>

// Fused conv1 -> conv2 -> SIFT128 -> linear -> softmax, one CTA/image.
// Round 6: R4 structure (best: 367us) + R5's validated stride-33 a1 padding
// (kills the 4-way LDS.64 bank conflicts in conv2 activation loads).

__constant__ float c_b1[32];
__constant__ float c_b2[3];
__constant__ float c_bl[10];

typedef unsigned long long u64;

// packed weight tables: [0,144) conv1 (w_even,w_odd) pairs; [144,576) conv2
__device__ __align__(16) float2 g_wpk[576];

__device__ __forceinline__ void fma2(u64& d, u64 a, u64 b) {
    asm("fma.rn.f32x2 %0, %1, %2, %0;" : "+l"(d) : "l"(a), "l"(b));
}
__device__ __forceinline__ u64 pk2(float lo, float hi) {
    u64 r; asm("mov.b64 %0, {%1, %2};" : "=l"(r) : "f"(lo), "f"(hi)); return r;
}
__device__ __forceinline__ float2 upk(u64 v) {
    float2 f; asm("mov.b64 {%0, %1}, %2;" : "=f"(f.x), "=f"(f.y) : "l"(v)); return f;
}

#define A1_ROW  33                       // u64 row stride (odd -> conflict-free)
#define A1_CP   858                      // 26 * 33 u64 per channel-pair

// shared layout (floats)
#define SM_XSPL    0                     // 28 rows x 30 cols splat pairs -> 1680
#define SM_A1P     1680                  // 4 ch-pairs x A1_CP u64 -> 6864 f
#define SM_A2P     (SM_A1P + 6864)       // 3 ch padded 26x26 -> 2028
#define SM_CELLS   (SM_A2P + 2028)       // 384
#define SM_NORMS   (SM_CELLS + 384)      // 4
#define SM_LOGITS  (SM_NORMS + 4)        // 12
#define SM_WPK     (SM_LOGITS + 12)      // 10972 (16B aligned): 576 u64 = 1152 f
#define SM_FLOATS  (SM_WPK + 1152)       // 12124 floats = 48496 B

__global__ void pack_weights(const float* __restrict__ W1,
                             const float* __restrict__ W2)
{
    int i = threadIdx.x + blockIdx.x * blockDim.x;
    if (i < 144) {
        int p = i / 9, k = i % 9;
        g_wpk[i] = make_float2(W1[(2 * p) * 9 + k], W1[(2 * p + 1) * 9 + k]);
    } else if (i < 576) {
        int j = i - 144;
        int oc = j / 144, r = j % 144;
        int icp = r / 9, tap = r % 9;
        g_wpk[i] = make_float2(W2[oc * 288 + (2 * icp) * 9 + tap],
                               W2[oc * 288 + (2 * icp + 1) * 9 + tap]);
    }
}

__global__ __launch_bounds__(256, 3)
void fused_sift_net(const float* __restrict__ x,
                    const float* __restrict__ Wl,
                    float* __restrict__ out)
{
    extern __shared__ float sm[];
    const int tid = threadIdx.x;
    const int img = blockIdx.x;

    // ---------------- Phase 0: splat image, stage weights, zero a2 ---------
    {
        const float4* xg = (const float4*)(x + (size_t)img * 784);
        float4* xs = (float4*)&sm[SM_XSPL];
        for (int i4 = tid; i4 < 196; i4 += 256) {
            float4 v = __ldg(&xg[i4]);
            int li = i4 * 4;
            int r = li / 28, c = li % 28;          // c multiple of 4
            int fi = (r * 30 + c) >> 1;            // float4 index (16B aligned)
            xs[fi]     = make_float4(v.x, v.x, v.y, v.y);
            xs[fi + 1] = make_float4(v.z, v.z, v.w, v.w);
        }
        const float4* gw = (const float4*)g_wpk;
        float4* swp = (float4*)&sm[SM_WPK];
        for (int i = tid; i < 288; i += 256) swp[i] = __ldg(&gw[i]);
        for (int i = tid; i < 2028; i += 256) sm[SM_A2P + i] = 0.0f;
    }

    // conv2 persistent accumulators: 96 threads, 1 out-row x 6-px strip
    const int c2row = tid >> 2;          // 0..23 (valid when tid<96)
    const int c2xb  = (tid & 3) * 6;     // 0,6,12,18
    u64 acc[3][6];
    if (tid < 96) {
#pragma unroll
        for (int oc = 0; oc < 3; oc++) {
            u64 bp = pk2(c_b2[oc], 0.0f);    // bias once in lo half
#pragma unroll
            for (int j = 0; j < 6; j++) acc[oc][j] = bp;
        }
    }

    const u64* wpk1 = (const u64*)&sm[SM_WPK];
    const u64* wpk2 = wpk1 + 144;
    const u64* xspl = (const u64*)&sm[SM_XSPL];
    u64* a1u = (u64*)&sm[SM_A1P];

    // ---------------- Phases 1-2: 4 chunks of 8 channels (4 pairs) ---------
    for (int chunk = 0; chunk < 4; chunk++) {
        __syncthreads();

        // conv1: 208 tasks = 4 pairs x 26 rows x 2 halves (13 cols each)
        if (tid < 208) {
            int pl   = tid / 52;
            int tt   = tid % 52;
            int row  = tt >> 1;
            int half = tt & 1;
            int gp   = chunk * 4 + pl;
            const u64* ws = wpk1 + gp * 9;
            u64 w0 = ws[0], w1 = ws[1], w2 = ws[2];
            u64 w3 = ws[3], w4 = ws[4], w5 = ws[5];
            u64 w6 = ws[6], w7 = ws[7], w8 = ws[8];
            u64 bp = pk2(c_b1[2 * gp], c_b1[2 * gp + 1]);
            const u64* xr = xspl + row * 30 + half * 13;
            u64 t00 = xr[0],  t01 = xr[1];
            u64 t10 = xr[30], t11 = xr[31];
            u64 t20 = xr[60], t21 = xr[61];
            float2* o = (float2*)(a1u + pl * A1_CP + row * A1_ROW + half * 13);
#pragma unroll
            for (int s = 0; s < 13; s++) {
                u64 n0 = xr[s + 2], n1 = xr[s + 32], n2 = xr[s + 62];
                u64 a = bp;
                fma2(a, t00, w0); fma2(a, t01, w1); fma2(a, n0, w2);
                fma2(a, t10, w3); fma2(a, t11, w4); fma2(a, n1, w5);
                fma2(a, t20, w6); fma2(a, t21, w7); fma2(a, n2, w8);
                float2 f = upk(a);
                o[s] = make_float2(fmaxf(f.x, 0.0f), fmaxf(f.y, 0.0f));
                t00 = t01; t01 = n0;
                t10 = t11; t11 = n1;
                t20 = t21; t21 = n2;
            }
        }
        __syncthreads();

        // conv2: 4 input-channel pairs, acts via conflict-free LDS.64
        if (tid < 96) {
#pragma unroll
            for (int icp = 0; icp < 4; icp++) {
                const u64* ap = a1u + icp * A1_CP + c2row * A1_ROW + c2xb;
                int gicp = chunk * 4 + icp;
#pragma unroll
                for (int dy = 0; dy < 3; dy++) {
                    u64 v[8];
#pragma unroll
                    for (int j = 0; j < 8; j++) v[j] = ap[dy * A1_ROW + j];
#pragma unroll
                    for (int oc = 0; oc < 3; oc++) {
                        const u64* wo = wpk2 + (oc * 16 + gicp) * 9 + dy * 3;
                        u64 wa = wo[0], wb = wo[1], wc = wo[2];
#pragma unroll
                        for (int j = 0; j < 6; j++) {
                            fma2(acc[oc][j], v[j],     wa);
                            fma2(acc[oc][j], v[j + 1], wb);
                            fma2(acc[oc][j], v[j + 2], wc);
                        }
                    }
                }
            }
        }
    }

    // conv2 outputs -> padded tile (scalar = lo + hi)
    if (tid < 96) {
#pragma unroll
        for (int oc = 0; oc < 3; oc++) {
            float* dst = &sm[SM_A2P + oc * 676 + (c2row + 1) * 26 + (c2xb + 1)];
#pragma unroll
            for (int j = 0; j < 6; j++) {
                float2 f = upk(acc[oc][j]);
                dst[j] = f.x + f.y;
            }
        }
    }
    __syncthreads();

    // ---------------- Phase 3: SIFT, register histograms --------------------
    if (tid < 192) {
        const float CS[8] = { 0.92387953f,  0.38268343f, -0.38268343f, -0.92387953f,
                             -0.92387953f, -0.38268343f,  0.38268343f,  0.92387953f};
        const float SN[8] = { 0.38268343f,  0.92387953f,  0.92387953f,  0.38268343f,
                             -0.38268343f, -0.92387953f, -0.92387953f, -0.38268343f};
        int p    = tid / 64;
        int rem  = tid % 64;
        int cell = rem >> 2;
        int quad = rem & 3;
        int r0 = (cell >> 2) * 6 + (quad >> 1) * 3;
        int c0 = (cell & 3) * 6 + (quad & 1) * 3;
        const float* ap = &sm[SM_A2P + p * 676 + r0 * 26 + c0];
        float pt[5][5];
#pragma unroll
        for (int i = 0; i < 5; i++)
#pragma unroll
            for (int j = 0; j < 5; j++) pt[i][j] = ap[i * 26 + j];

        float hist[8] = {0,0,0,0,0,0,0,0};
#pragma unroll
        for (int i = 0; i < 3; i++) {
#pragma unroll
            for (int j = 0; j < 3; j++) {
                float Ix = (pt[i][j+2] - pt[i][j])
                         + 2.0f * (pt[i+1][j+2] - pt[i+1][j])
                         + (pt[i+2][j+2] - pt[i+2][j]);
                float Iy = (pt[i+2][j] - pt[i][j])
                         + 2.0f * (pt[i+2][j+1] - pt[i][j+1])
                         + (pt[i+2][j+2] - pt[i][j+2]);
                float mag = sqrtf(Ix * Ix + Iy * Iy + 1e-12f);
                float ck[8];
                float cmax = -1e30f;
#pragma unroll
                for (int k = 0; k < 8; k++) {
                    ck[k] = CS[k] * Ix + SN[k] * Iy;
                    cmax = fmaxf(cmax, ck[k]);
                }
#pragma unroll
                for (int k = 0; k < 8; k++)
                    hist[k] += (ck[k] == cmax) ? mag : 0.0f;
            }
        }
#pragma unroll
        for (int k = 0; k < 8; k++) {
            float v = hist[k];
            v += __shfl_xor_sync(0xffffffffu, v, 1);
            v += __shfl_xor_sync(0xffffffffu, v, 2);
            if (quad == 0)
                sm[SM_CELLS + p * 128 + k * 16 + cell] = v;
        }
    }
    __syncthreads();

    // ---------------- Phase 4: norms + pow 0.9 ------------------------------
    if (tid < 96) {
        int w = tid >> 5, lane = tid & 31;
        const float* cp = &sm[SM_CELLS + w * 128];
        float s = 0.0f;
#pragma unroll
        for (int j = 0; j < 4; j++) {
            float v = cp[lane + 32 * j];
            s = fmaf(v, v, s);
        }
#pragma unroll
        for (int d = 16; d; d >>= 1)
            s += __shfl_xor_sync(0xffffffffu, s, d);
        if (lane == 0) sm[SM_NORMS + w] = sqrtf(s);
    }
    __syncthreads();
    {
        int i = tid;
        if (i < 384) {
            float v = sm[SM_CELLS + i];
            float f = v / (sm[SM_NORMS + (i >> 7)] + 1e-8f);
            sm[SM_CELLS + i] = powf(f + 1e-8f, 0.9f);
        }
        i = tid + 256;
        if (i < 384) {
            float v = sm[SM_CELLS + i];
            float f = v / (sm[SM_NORMS + (i >> 7)] + 1e-8f);
            sm[SM_CELLS + i] = powf(f + 1e-8f, 0.9f);
        }
    }
    __syncthreads();

    // ---------------- Phase 5: 384x10 linear --------------------------------
    {
        int w = tid >> 5, lane = tid & 31;
#pragma unroll
        for (int rep = 0; rep < 2; rep++) {
            int o = w + rep * 8;
            if (o < 10) {
                float s = 0.0f;
                const float* wrow = Wl + o * 384;
                for (int i = lane; i < 384; i += 32)
                    s = fmaf(sm[SM_CELLS + i], __ldg(&wrow[i]), s);
#pragma unroll
                for (int d = 16; d; d >>= 1)
                    s += __shfl_xor_sync(0xffffffffu, s, d);
                if (lane == 0) sm[SM_LOGITS + o] = s + c_bl[o];
            }
        }
    }
    __syncthreads();

    // ---------------- Phase 6: relu + softmax -------------------------------
    if (tid < 32) {
        float v = (tid < 10) ? fmaxf(sm[SM_LOGITS + tid], 0.0f) : -1e30f;
        float m = v;
#pragma unroll
        for (int d = 16; d; d >>= 1)
            m = fmaxf(m, __shfl_xor_sync(0xffffffffu, m, d));
        float e = (tid < 10) ? expf(v - m) : 0.0f;
        float ssum = e;
#pragma unroll
        for (int d = 16; d; d >>= 1)
            ssum += __shfl_xor_sync(0xffffffffu, ssum, d);
        if (tid < 10) out[(size_t)img * 10 + tid] = e / ssum;
    }
}

extern "C" void kernel_launch(void* const* d_in, const int* in_sizes, int n_in,
                              void* d_out, int out_size)
{
    const float* x  = (const float*)d_in[0];
    const float* W1 = (const float*)d_in[1];
    const float* b1 = (const float*)d_in[2];
    const float* W2 = (const float*)d_in[3];
    const float* b2 = (const float*)d_in[4];
    const float* Wl = (const float*)d_in[5];
    const float* bl = (const float*)d_in[6];

    int nimg = in_sizes[0] / 784;

    cudaMemcpyToSymbolAsync(c_b1, b1, 32 * sizeof(float), 0, cudaMemcpyDeviceToDevice, 0);
    cudaMemcpyToSymbolAsync(c_b2, b2,  3 * sizeof(float), 0, cudaMemcpyDeviceToDevice, 0);
    cudaMemcpyToSymbolAsync(c_bl, bl, 10 * sizeof(float), 0, cudaMemcpyDeviceToDevice, 0);

    pack_weights<<<3, 256>>>(W1, W2);

    size_t smem = SM_FLOATS * sizeof(float);
    cudaFuncSetAttribute(fused_sift_net,
                         cudaFuncAttributeMaxDynamicSharedMemorySize, (int)smem);

    fused_sift_net<<<nimg, 256, smem>>>(x, Wl, (float*)d_out);
}

// round 7
// speedup vs baseline: 1.0717x; 1.0083x over previous
#include <cuda_runtime.h>

// Fused conv1 -> conv2 -> SIFT128 -> linear -> softmax, one CTA/image.
// Round 7: R4 structure + packed weights in __constant__ (LDCU port, off the
// L1 crossbar) + even stride-36 a1 (2-way max conflicts, LDS.128-alignable).

__constant__ float c_b1[32];
__constant__ float c_b2[3];
__constant__ float c_bl[10];
// packed weights: [0,144) conv1 (w_even,w_odd); [144,576) conv2
__constant__ __align__(16) float2 c_wpk[576];

// staging buffer written by pack_weights, then copied into c_wpk
__device__ __align__(16) float2 g_wpk[576];

typedef unsigned long long u64;

__device__ __forceinline__ void fma2(u64& d, u64 a, u64 b) {
    asm("fma.rn.f32x2 %0, %1, %2, %0;" : "+l"(d) : "l"(a), "l"(b));
}
__device__ __forceinline__ u64 pk2(float lo, float hi) {
    u64 r; asm("mov.b64 %0, {%1, %2};" : "=l"(r) : "f"(lo), "f"(hi)); return r;
}
__device__ __forceinline__ float2 upk(u64 v) {
    float2 f; asm("mov.b64 {%0, %1}, %2;" : "=f"(f.x), "=f"(f.y) : "l"(v)); return f;
}

#define A1_ROW  36                       // u64 row stride (even, 2-way max)
#define A1_CP   936                      // 26 * 36 u64 per channel-pair

// shared layout (floats)
#define SM_XSPL    0                     // 28 rows x 30 cols splat pairs -> 1680
#define SM_A1P     1680                  // 4 ch-pairs x A1_CP u64 -> 7488 f
#define SM_A2P     (SM_A1P + 7488)       // 3 ch padded 26x26 -> 2028
#define SM_CELLS   (SM_A2P + 2028)       // 384
#define SM_NORMS   (SM_CELLS + 384)      // 4
#define SM_LOGITS  (SM_NORMS + 4)        // 12
#define SM_FLOATS  (SM_LOGITS + 12)      // 11596 floats = 46384 B

__global__ void pack_weights(const float* __restrict__ W1,
                             const float* __restrict__ W2)
{
    int i = threadIdx.x + blockIdx.x * blockDim.x;
    if (i < 144) {
        int p = i / 9, k = i % 9;
        g_wpk[i] = make_float2(W1[(2 * p) * 9 + k], W1[(2 * p + 1) * 9 + k]);
    } else if (i < 576) {
        int j = i - 144;
        int oc = j / 144, r = j % 144;
        int icp = r / 9, tap = r % 9;
        g_wpk[i] = make_float2(W2[oc * 288 + (2 * icp) * 9 + tap],
                               W2[oc * 288 + (2 * icp + 1) * 9 + tap]);
    }
}

__global__ __launch_bounds__(256, 3)
void fused_sift_net(const float* __restrict__ x,
                    const float* __restrict__ Wl,
                    float* __restrict__ out)
{
    extern __shared__ float sm[];
    const int tid = threadIdx.x;
    const int img = blockIdx.x;

    // ---------------- Phase 0: splat image, zero a2 ------------------------
    {
        const float4* xg = (const float4*)(x + (size_t)img * 784);
        float4* xs = (float4*)&sm[SM_XSPL];
        for (int i4 = tid; i4 < 196; i4 += 256) {
            float4 v = __ldg(&xg[i4]);
            int li = i4 * 4;
            int r = li / 28, c = li % 28;          // c multiple of 4
            int fi = (r * 30 + c) >> 1;            // float4 index (16B aligned)
            xs[fi]     = make_float4(v.x, v.x, v.y, v.y);
            xs[fi + 1] = make_float4(v.z, v.z, v.w, v.w);
        }
        for (int i = tid; i < 2028; i += 256) sm[SM_A2P + i] = 0.0f;
    }

    // conv2 persistent accumulators: 96 threads, 1 out-row x 6-px strip
    const int c2row = tid >> 2;          // 0..23 (valid when tid<96)
    const int c2xb  = (tid & 3) * 6;     // 0,6,12,18
    u64 acc[3][6];
    if (tid < 96) {
#pragma unroll
        for (int oc = 0; oc < 3; oc++) {
            u64 bp = pk2(c_b2[oc], 0.0f);    // bias once in lo half
#pragma unroll
            for (int j = 0; j < 6; j++) acc[oc][j] = bp;
        }
    }

    const u64* wpk1 = (const u64*)c_wpk;        // constant bank (LDC/LDCU)
    const u64* wpk2 = wpk1 + 144;
    const u64* xspl = (const u64*)&sm[SM_XSPL];
    u64* a1u = (u64*)&sm[SM_A1P];

    // ---------------- Phases 1-2: 4 chunks of 8 channels (4 pairs) ---------
    for (int chunk = 0; chunk < 4; chunk++) {
        __syncthreads();

        // conv1: 208 tasks = 4 pairs x 26 rows x 2 halves (13 cols each)
        if (tid < 208) {
            int pl   = tid / 52;
            int tt   = tid % 52;
            int row  = tt >> 1;
            int half = tt & 1;
            int gp   = chunk * 4 + pl;
            const u64* ws = wpk1 + gp * 9;
            u64 w0 = ws[0], w1 = ws[1], w2 = ws[2];
            u64 w3 = ws[3], w4 = ws[4], w5 = ws[5];
            u64 w6 = ws[6], w7 = ws[7], w8 = ws[8];
            u64 bp = pk2(c_b1[2 * gp], c_b1[2 * gp + 1]);
            const u64* xr = xspl + row * 30 + half * 13;
            u64 t00 = xr[0],  t01 = xr[1];
            u64 t10 = xr[30], t11 = xr[31];
            u64 t20 = xr[60], t21 = xr[61];
            float2* o = (float2*)(a1u + pl * A1_CP + row * A1_ROW + half * 13);
#pragma unroll
            for (int s = 0; s < 13; s++) {
                u64 n0 = xr[s + 2], n1 = xr[s + 32], n2 = xr[s + 62];
                u64 a = bp;
                fma2(a, t00, w0); fma2(a, t01, w1); fma2(a, n0, w2);
                fma2(a, t10, w3); fma2(a, t11, w4); fma2(a, n1, w5);
                fma2(a, t20, w6); fma2(a, t21, w7); fma2(a, n2, w8);
                float2 f = upk(a);
                o[s] = make_float2(fmaxf(f.x, 0.0f), fmaxf(f.y, 0.0f));
                t00 = t01; t01 = n0;
                t10 = t11; t11 = n1;
                t20 = t21; t21 = n2;
            }
        }
        __syncthreads();

        // conv2: 4 input-channel pairs; acts from smem, weights from const
        if (tid < 96) {
#pragma unroll
            for (int icp = 0; icp < 4; icp++) {
                const u64* ap = a1u + icp * A1_CP + c2row * A1_ROW + c2xb;
                int gicp = chunk * 4 + icp;
#pragma unroll
                for (int dy = 0; dy < 3; dy++) {
                    u64 v[8];
#pragma unroll
                    for (int j = 0; j < 8; j++) v[j] = ap[dy * A1_ROW + j];
#pragma unroll
                    for (int oc = 0; oc < 3; oc++) {
                        const u64* wo = wpk2 + (oc * 16 + gicp) * 9 + dy * 3;
                        u64 wa = wo[0], wb = wo[1], wc = wo[2];
#pragma unroll
                        for (int j = 0; j < 6; j++) {
                            fma2(acc[oc][j], v[j],     wa);
                            fma2(acc[oc][j], v[j + 1], wb);
                            fma2(acc[oc][j], v[j + 2], wc);
                        }
                    }
                }
            }
        }
    }

    // conv2 outputs -> padded tile (scalar = lo + hi)
    if (tid < 96) {
#pragma unroll
        for (int oc = 0; oc < 3; oc++) {
            float* dst = &sm[SM_A2P + oc * 676 + (c2row + 1) * 26 + (c2xb + 1)];
#pragma unroll
            for (int j = 0; j < 6; j++) {
                float2 f = upk(acc[oc][j]);
                dst[j] = f.x + f.y;
            }
        }
    }
    __syncthreads();

    // ---------------- Phase 3: SIFT, register histograms --------------------
    if (tid < 192) {
        const float CS[8] = { 0.92387953f,  0.38268343f, -0.38268343f, -0.92387953f,
                             -0.92387953f, -0.38268343f,  0.38268343f,  0.92387953f};
        const float SN[8] = { 0.38268343f,  0.92387953f,  0.92387953f,  0.38268343f,
                             -0.38268343f, -0.92387953f, -0.92387953f, -0.38268343f};
        int p    = tid / 64;
        int rem  = tid % 64;
        int cell = rem >> 2;
        int quad = rem & 3;
        int r0 = (cell >> 2) * 6 + (quad >> 1) * 3;
        int c0 = (cell & 3) * 6 + (quad & 1) * 3;
        const float* ap = &sm[SM_A2P + p * 676 + r0 * 26 + c0];
        float pt[5][5];
#pragma unroll
        for (int i = 0; i < 5; i++)
#pragma unroll
            for (int j = 0; j < 5; j++) pt[i][j] = ap[i * 26 + j];

        float hist[8] = {0,0,0,0,0,0,0,0};
#pragma unroll
        for (int i = 0; i < 3; i++) {
#pragma unroll
            for (int j = 0; j < 3; j++) {
                float Ix = (pt[i][j+2] - pt[i][j])
                         + 2.0f * (pt[i+1][j+2] - pt[i+1][j])
                         + (pt[i+2][j+2] - pt[i+2][j]);
                float Iy = (pt[i+2][j] - pt[i][j])
                         + 2.0f * (pt[i+2][j+1] - pt[i][j+1])
                         + (pt[i+2][j+2] - pt[i][j+2]);
                float mag = sqrtf(Ix * Ix + Iy * Iy + 1e-12f);
                float ck[8];
                float cmax = -1e30f;
#pragma unroll
                for (int k = 0; k < 8; k++) {
                    ck[k] = CS[k] * Ix + SN[k] * Iy;
                    cmax = fmaxf(cmax, ck[k]);
                }
#pragma unroll
                for (int k = 0; k < 8; k++)
                    hist[k] += (ck[k] == cmax) ? mag : 0.0f;
            }
        }
#pragma unroll
        for (int k = 0; k < 8; k++) {
            float v = hist[k];
            v += __shfl_xor_sync(0xffffffffu, v, 1);
            v += __shfl_xor_sync(0xffffffffu, v, 2);
            if (quad == 0)
                sm[SM_CELLS + p * 128 + k * 16 + cell] = v;
        }
    }
    __syncthreads();

    // ---------------- Phase 4: norms + pow 0.9 ------------------------------
    if (tid < 96) {
        int w = tid >> 5, lane = tid & 31;
        const float* cp = &sm[SM_CELLS + w * 128];
        float s = 0.0f;
#pragma unroll
        for (int j = 0; j < 4; j++) {
            float v = cp[lane + 32 * j];
            s = fmaf(v, v, s);
        }
#pragma unroll
        for (int d = 16; d; d >>= 1)
            s += __shfl_xor_sync(0xffffffffu, s, d);
        if (lane == 0) sm[SM_NORMS + w] = sqrtf(s);
    }
    __syncthreads();
    {
        int i = tid;
        if (i < 384) {
            float v = sm[SM_CELLS + i];
            float f = v / (sm[SM_NORMS + (i >> 7)] + 1e-8f);
            sm[SM_CELLS + i] = powf(f + 1e-8f, 0.9f);
        }
        i = tid + 256;
        if (i < 384) {
            float v = sm[SM_CELLS + i];
            float f = v / (sm[SM_NORMS + (i >> 7)] + 1e-8f);
            sm[SM_CELLS + i] = powf(f + 1e-8f, 0.9f);
        }
    }
    __syncthreads();

    // ---------------- Phase 5: 384x10 linear --------------------------------
    {
        int w = tid >> 5, lane = tid & 31;
#pragma unroll
        for (int rep = 0; rep < 2; rep++) {
            int o = w + rep * 8;
            if (o < 10) {
                float s = 0.0f;
                const float* wrow = Wl + o * 384;
                for (int i = lane; i < 384; i += 32)
                    s = fmaf(sm[SM_CELLS + i], __ldg(&wrow[i]), s);
#pragma unroll
                for (int d = 16; d; d >>= 1)
                    s += __shfl_xor_sync(0xffffffffu, s, d);
                if (lane == 0) sm[SM_LOGITS + o] = s + c_bl[o];
            }
        }
    }
    __syncthreads();

    // ---------------- Phase 6: relu + softmax -------------------------------
    if (tid < 32) {
        float v = (tid < 10) ? fmaxf(sm[SM_LOGITS + tid], 0.0f) : -1e30f;
        float m = v;
#pragma unroll
        for (int d = 16; d; d >>= 1)
            m = fmaxf(m, __shfl_xor_sync(0xffffffffu, m, d));
        float e = (tid < 10) ? expf(v - m) : 0.0f;
        float ssum = e;
#pragma unroll
        for (int d = 16; d; d >>= 1)
            ssum += __shfl_xor_sync(0xffffffffu, ssum, d);
        if (tid < 10) out[(size_t)img * 10 + tid] = e / ssum;
    }
}

extern "C" void kernel_launch(void* const* d_in, const int* in_sizes, int n_in,
                              void* d_out, int out_size)
{
    const float* x  = (const float*)d_in[0];
    const float* W1 = (const float*)d_in[1];
    const float* b1 = (const float*)d_in[2];
    const float* W2 = (const float*)d_in[3];
    const float* b2 = (const float*)d_in[4];
    const float* Wl = (const float*)d_in[5];
    const float* bl = (const float*)d_in[6];

    int nimg = in_sizes[0] / 784;

    cudaMemcpyToSymbolAsync(c_b1, b1, 32 * sizeof(float), 0, cudaMemcpyDeviceToDevice, 0);
    cudaMemcpyToSymbolAsync(c_b2, b2,  3 * sizeof(float), 0, cudaMemcpyDeviceToDevice, 0);
    cudaMemcpyToSymbolAsync(c_bl, bl, 10 * sizeof(float), 0, cudaMemcpyDeviceToDevice, 0);

    // pack into device staging, then stage -> constant bank (D2D memcpy node)
    pack_weights<<<3, 256>>>(W1, W2);
    void* gsrc = nullptr;
    cudaGetSymbolAddress(&gsrc, g_wpk);
    cudaMemcpyToSymbolAsync(c_wpk, gsrc, 576 * sizeof(float2), 0,
                            cudaMemcpyDeviceToDevice, 0);

    size_t smem = SM_FLOATS * sizeof(float);
    cudaFuncSetAttribute(fused_sift_net,
                         cudaFuncAttributeMaxDynamicSharedMemorySize, (int)smem);

    fused_sift_net<<<nimg, 256, smem>>>(x, Wl, (float*)d_out);
}

// round 8
// speedup vs baseline: 1.1016x; 1.0278x over previous
#include <cuda_runtime.h>

// Fused conv1 -> conv2 -> SIFT128 -> linear -> softmax, one CTA/image.
// Round 8: conv2 on 192 threads (9 accs/thread, lighter regs), 4 CTAs/SM.
// Weights in constant bank, stride-36 a1, FFMA2 throughout.

__constant__ float c_b1[32];
__constant__ float c_b2[3];
__constant__ float c_bl[10];
// packed weights: [0,144) conv1 (w_even,w_odd); [144,576) conv2
__constant__ __align__(16) float2 c_wpk[576];

// staging buffer written by pack_weights, then copied into c_wpk
__device__ __align__(16) float2 g_wpk[576];

typedef unsigned long long u64;

__device__ __forceinline__ void fma2(u64& d, u64 a, u64 b) {
    asm("fma.rn.f32x2 %0, %1, %2, %0;" : "+l"(d) : "l"(a), "l"(b));
}
__device__ __forceinline__ u64 pk2(float lo, float hi) {
    u64 r; asm("mov.b64 %0, {%1, %2};" : "=l"(r) : "f"(lo), "f"(hi)); return r;
}
__device__ __forceinline__ float2 upk(u64 v) {
    float2 f; asm("mov.b64 {%0, %1}, %2;" : "=f"(f.x), "=f"(f.y) : "l"(v)); return f;
}

#define A1_ROW  36                       // u64 row stride
#define A1_CP   936                      // 26 * 36 u64 per channel-pair

// shared layout (floats)
#define SM_XSPL    0                     // 28 rows x 30 cols splat pairs -> 1680
#define SM_A1P     1680                  // 4 ch-pairs x A1_CP u64 -> 7488 f
#define SM_A2P     (SM_A1P + 7488)       // 3 ch padded 26x26 -> 2028
#define SM_CELLS   (SM_A2P + 2028)       // 384
#define SM_NORMS   (SM_CELLS + 384)      // 4
#define SM_LOGITS  (SM_NORMS + 4)        // 12
#define SM_FLOATS  (SM_LOGITS + 12)      // 11596 floats = 46384 B

__global__ void pack_weights(const float* __restrict__ W1,
                             const float* __restrict__ W2)
{
    int i = threadIdx.x + blockIdx.x * blockDim.x;
    if (i < 144) {
        int p = i / 9, k = i % 9;
        g_wpk[i] = make_float2(W1[(2 * p) * 9 + k], W1[(2 * p + 1) * 9 + k]);
    } else if (i < 576) {
        int j = i - 144;
        int oc = j / 144, r = j % 144;
        int icp = r / 9, tap = r % 9;
        g_wpk[i] = make_float2(W2[oc * 288 + (2 * icp) * 9 + tap],
                               W2[oc * 288 + (2 * icp + 1) * 9 + tap]);
    }
}

__global__ __launch_bounds__(256, 4)
void fused_sift_net(const float* __restrict__ x,
                    const float* __restrict__ Wl,
                    float* __restrict__ out)
{
    extern __shared__ float sm[];
    const int tid = threadIdx.x;
    const int img = blockIdx.x;

    // ---------------- Phase 0: splat image, zero a2 ------------------------
    {
        const float4* xg = (const float4*)(x + (size_t)img * 784);
        float4* xs = (float4*)&sm[SM_XSPL];
        for (int i4 = tid; i4 < 196; i4 += 256) {
            float4 v = __ldg(&xg[i4]);
            int li = i4 * 4;
            int r = li / 28, c = li % 28;          // c multiple of 4
            int fi = (r * 30 + c) >> 1;            // float4 index (16B aligned)
            xs[fi]     = make_float4(v.x, v.x, v.y, v.y);
            xs[fi + 1] = make_float4(v.z, v.z, v.w, v.w);
        }
        for (int i = tid; i < 2028; i += 256) sm[SM_A2P + i] = 0.0f;
    }

    // conv2 persistent accumulators: 192 threads, 1 out-row x 3-px strip x 3 oc
    const int c2row = tid >> 3;          // 0..23 (valid when tid<192)
    const int c2xs  = (tid & 7) * 3;     // 0,3,...,21
    u64 acc[3][3];
    if (tid < 192) {
#pragma unroll
        for (int oc = 0; oc < 3; oc++) {
            u64 bp = pk2(c_b2[oc], 0.0f);    // bias once in lo half
#pragma unroll
            for (int j = 0; j < 3; j++) acc[oc][j] = bp;
        }
    }

    const u64* wpk1 = (const u64*)c_wpk;        // constant bank
    const u64* wpk2 = wpk1 + 144;
    const u64* xspl = (const u64*)&sm[SM_XSPL];
    u64* a1u = (u64*)&sm[SM_A1P];

    // ---------------- Phases 1-2: 4 chunks of 8 channels (4 pairs) ---------
    for (int chunk = 0; chunk < 4; chunk++) {
        __syncthreads();

        // conv1: 208 tasks = 4 pairs x 26 rows x 2 halves (13 cols each)
        if (tid < 208) {
            int pl   = tid / 52;
            int tt   = tid % 52;
            int row  = tt >> 1;
            int half = tt & 1;
            int gp   = chunk * 4 + pl;
            const u64* ws = wpk1 + gp * 9;
            u64 w0 = ws[0], w1 = ws[1], w2 = ws[2];
            u64 w3 = ws[3], w4 = ws[4], w5 = ws[5];
            u64 w6 = ws[6], w7 = ws[7], w8 = ws[8];
            u64 bp = pk2(c_b1[2 * gp], c_b1[2 * gp + 1]);
            const u64* xr = xspl + row * 30 + half * 13;
            u64 t00 = xr[0],  t01 = xr[1];
            u64 t10 = xr[30], t11 = xr[31];
            u64 t20 = xr[60], t21 = xr[61];
            float2* o = (float2*)(a1u + pl * A1_CP + row * A1_ROW + half * 13);
#pragma unroll
            for (int s = 0; s < 13; s++) {
                u64 n0 = xr[s + 2], n1 = xr[s + 32], n2 = xr[s + 62];
                u64 a = bp;
                fma2(a, t00, w0); fma2(a, t01, w1); fma2(a, n0, w2);
                fma2(a, t10, w3); fma2(a, t11, w4); fma2(a, n1, w5);
                fma2(a, t20, w6); fma2(a, t21, w7); fma2(a, n2, w8);
                float2 f = upk(a);
                o[s] = make_float2(fmaxf(f.x, 0.0f), fmaxf(f.y, 0.0f));
                t00 = t01; t01 = n0;
                t10 = t11; t11 = n1;
                t20 = t21; t21 = n2;
            }
        }
        __syncthreads();

        // conv2: 4 input-channel pairs; acts from smem, weights from const
        if (tid < 192) {
#pragma unroll
            for (int icp = 0; icp < 4; icp++) {
                const u64* ap = a1u + icp * A1_CP + c2row * A1_ROW + c2xs;
                int gicp = chunk * 4 + icp;
#pragma unroll
                for (int dy = 0; dy < 3; dy++) {
                    u64 v0 = ap[dy * A1_ROW + 0];
                    u64 v1 = ap[dy * A1_ROW + 1];
                    u64 v2 = ap[dy * A1_ROW + 2];
                    u64 v3 = ap[dy * A1_ROW + 3];
                    u64 v4 = ap[dy * A1_ROW + 4];
#pragma unroll
                    for (int oc = 0; oc < 3; oc++) {
                        const u64* wo = wpk2 + (oc * 16 + gicp) * 9 + dy * 3;
                        u64 wa = wo[0], wb = wo[1], wc = wo[2];
                        fma2(acc[oc][0], v0, wa);
                        fma2(acc[oc][1], v1, wa);
                        fma2(acc[oc][2], v2, wa);
                        fma2(acc[oc][0], v1, wb);
                        fma2(acc[oc][1], v2, wb);
                        fma2(acc[oc][2], v3, wb);
                        fma2(acc[oc][0], v2, wc);
                        fma2(acc[oc][1], v3, wc);
                        fma2(acc[oc][2], v4, wc);
                    }
                }
            }
        }
    }

    // conv2 outputs -> padded tile (scalar = lo + hi)
    if (tid < 192) {
#pragma unroll
        for (int oc = 0; oc < 3; oc++) {
            float* dst = &sm[SM_A2P + oc * 676 + (c2row + 1) * 26 + (c2xs + 1)];
#pragma unroll
            for (int j = 0; j < 3; j++) {
                float2 f = upk(acc[oc][j]);
                dst[j] = f.x + f.y;
            }
        }
    }
    __syncthreads();

    // ---------------- Phase 3: SIFT, register histograms --------------------
    if (tid < 192) {
        const float CS[8] = { 0.92387953f,  0.38268343f, -0.38268343f, -0.92387953f,
                             -0.92387953f, -0.38268343f,  0.38268343f,  0.92387953f};
        const float SN[8] = { 0.38268343f,  0.92387953f,  0.92387953f,  0.38268343f,
                             -0.38268343f, -0.92387953f, -0.92387953f, -0.38268343f};
        int p    = tid / 64;
        int rem  = tid % 64;
        int cell = rem >> 2;
        int quad = rem & 3;
        int r0 = (cell >> 2) * 6 + (quad >> 1) * 3;
        int c0 = (cell & 3) * 6 + (quad & 1) * 3;
        const float* ap = &sm[SM_A2P + p * 676 + r0 * 26 + c0];
        float pt[5][5];
#pragma unroll
        for (int i = 0; i < 5; i++)
#pragma unroll
            for (int j = 0; j < 5; j++) pt[i][j] = ap[i * 26 + j];

        float hist[8] = {0,0,0,0,0,0,0,0};
#pragma unroll
        for (int i = 0; i < 3; i++) {
#pragma unroll
            for (int j = 0; j < 3; j++) {
                float Ix = (pt[i][j+2] - pt[i][j])
                         + 2.0f * (pt[i+1][j+2] - pt[i+1][j])
                         + (pt[i+2][j+2] - pt[i+2][j]);
                float Iy = (pt[i+2][j] - pt[i][j])
                         + 2.0f * (pt[i+2][j+1] - pt[i][j+1])
                         + (pt[i+2][j+2] - pt[i][j+2]);
                float mag = sqrtf(Ix * Ix + Iy * Iy + 1e-12f);
                float ck[8];
                float cmax = -1e30f;
#pragma unroll
                for (int k = 0; k < 8; k++) {
                    ck[k] = CS[k] * Ix + SN[k] * Iy;
                    cmax = fmaxf(cmax, ck[k]);
                }
#pragma unroll
                for (int k = 0; k < 8; k++)
                    hist[k] += (ck[k] == cmax) ? mag : 0.0f;
            }
        }
#pragma unroll
        for (int k = 0; k < 8; k++) {
            float v = hist[k];
            v += __shfl_xor_sync(0xffffffffu, v, 1);
            v += __shfl_xor_sync(0xffffffffu, v, 2);
            if (quad == 0)
                sm[SM_CELLS + p * 128 + k * 16 + cell] = v;
        }
    }
    __syncthreads();

    // ---------------- Phase 4: norms + pow 0.9 ------------------------------
    if (tid < 96) {
        int w = tid >> 5, lane = tid & 31;
        const float* cp = &sm[SM_CELLS + w * 128];
        float s = 0.0f;
#pragma unroll
        for (int j = 0; j < 4; j++) {
            float v = cp[lane + 32 * j];
            s = fmaf(v, v, s);
        }
#pragma unroll
        for (int d = 16; d; d >>= 1)
            s += __shfl_xor_sync(0xffffffffu, s, d);
        if (lane == 0) sm[SM_NORMS + w] = sqrtf(s);
    }
    __syncthreads();
    {
        int i = tid;
        if (i < 384) {
            float v = sm[SM_CELLS + i];
            float f = v / (sm[SM_NORMS + (i >> 7)] + 1e-8f);
            sm[SM_CELLS + i] = powf(f + 1e-8f, 0.9f);
        }
        i = tid + 256;
        if (i < 384) {
            float v = sm[SM_CELLS + i];
            float f = v / (sm[SM_NORMS + (i >> 7)] + 1e-8f);
            sm[SM_CELLS + i] = powf(f + 1e-8f, 0.9f);
        }
    }
    __syncthreads();

    // ---------------- Phase 5: 384x10 linear --------------------------------
    {
        int w = tid >> 5, lane = tid & 31;
#pragma unroll
        for (int rep = 0; rep < 2; rep++) {
            int o = w + rep * 8;
            if (o < 10) {
                float s = 0.0f;
                const float* wrow = Wl + o * 384;
                for (int i = lane; i < 384; i += 32)
                    s = fmaf(sm[SM_CELLS + i], __ldg(&wrow[i]), s);
#pragma unroll
                for (int d = 16; d; d >>= 1)
                    s += __shfl_xor_sync(0xffffffffu, s, d);
                if (lane == 0) sm[SM_LOGITS + o] = s + c_bl[o];
            }
        }
    }
    __syncthreads();

    // ---------------- Phase 6: relu + softmax -------------------------------
    if (tid < 32) {
        float v = (tid < 10) ? fmaxf(sm[SM_LOGITS + tid], 0.0f) : -1e30f;
        float m = v;
#pragma unroll
        for (int d = 16; d; d >>= 1)
            m = fmaxf(m, __shfl_xor_sync(0xffffffffu, m, d));
        float e = (tid < 10) ? expf(v - m) : 0.0f;
        float ssum = e;
#pragma unroll
        for (int d = 16; d; d >>= 1)
            ssum += __shfl_xor_sync(0xffffffffu, ssum, d);
        if (tid < 10) out[(size_t)img * 10 + tid] = e / ssum;
    }
}

extern "C" void kernel_launch(void* const* d_in, const int* in_sizes, int n_in,
                              void* d_out, int out_size)
{
    const float* x  = (const float*)d_in[0];
    const float* W1 = (const float*)d_in[1];
    const float* b1 = (const float*)d_in[2];
    const float* W2 = (const float*)d_in[3];
    const float* b2 = (const float*)d_in[4];
    const float* Wl = (const float*)d_in[5];
    const float* bl = (const float*)d_in[6];

    int nimg = in_sizes[0] / 784;

    cudaMemcpyToSymbolAsync(c_b1, b1, 32 * sizeof(float), 0, cudaMemcpyDeviceToDevice, 0);
    cudaMemcpyToSymbolAsync(c_b2, b2,  3 * sizeof(float), 0, cudaMemcpyDeviceToDevice, 0);
    cudaMemcpyToSymbolAsync(c_bl, bl, 10 * sizeof(float), 0, cudaMemcpyDeviceToDevice, 0);

    pack_weights<<<3, 256>>>(W1, W2);
    void* gsrc = nullptr;
    cudaGetSymbolAddress(&gsrc, g_wpk);
    cudaMemcpyToSymbolAsync(c_wpk, gsrc, 576 * sizeof(float2), 0,
                            cudaMemcpyDeviceToDevice, 0);

    size_t smem = SM_FLOATS * sizeof(float);
    cudaFuncSetAttribute(fused_sift_net,
                         cudaFuncAttributeMaxDynamicSharedMemorySize, (int)smem);

    fused_sift_net<<<nimg, 256, smem>>>(x, Wl, (float*)d_out);
}